// round 10
// baseline (speedup 1.0000x reference)
#include <cuda_runtime.h>
#include <cuda_bf16.h>
#include <cstdint>

#define NUM_H 16
#define SEQ_T 2048
#define DIM   1024
#define HD    64

// ---------------- scratch (__device__ globals) -----------------------------
__device__ __align__(16) __nv_bfloat16 gA_hi[SEQ_T][DIM];
__device__ __align__(16) __nv_bfloat16 gA_lo[SEQ_T][DIM];
__device__ __align__(16) __nv_bfloat16 gBq_hi[3 * DIM][DIM];   // [N][K]
__device__ __align__(16) __nv_bfloat16 gBq_lo[3 * DIM][DIM];
__device__ __align__(16) __nv_bfloat16 gBp_hi[DIM][DIM];
__device__ __align__(16) __nv_bfloat16 gBp_lo[DIM][DIM];
__device__ __align__(16) __nv_bfloat16 gY_hi[SEQ_T][DIM];
__device__ __align__(16) __nv_bfloat16 gY_lo[SEQ_T][DIM];

// per-head split Q/K/V (Q pre-scaled by 1/8)
__device__ __align__(16) __nv_bfloat16 gQh[NUM_H][SEQ_T][HD];
__device__ __align__(16) __nv_bfloat16 gQl[NUM_H][SEQ_T][HD];
__device__ __align__(16) __nv_bfloat16 gKh[NUM_H][SEQ_T][HD];
__device__ __align__(16) __nv_bfloat16 gKl[NUM_H][SEQ_T][HD];
__device__ __align__(16) __nv_bfloat16 gVh[NUM_H][SEQ_T][HD];
__device__ __align__(16) __nv_bfloat16 gVl[NUM_H][SEQ_T][HD];

// ---------------- PTX helpers ----------------------------------------------
__device__ __forceinline__ uint32_t smem_u32(const void* p) {
    uint32_t a;
    asm("{ .reg .u64 t; cvta.to.shared.u64 t, %1; cvt.u32.u64 %0, t; }" : "=r"(a) : "l"(p));
    return a;
}
#define CP_ASYNC16(dst, src) \
    asm volatile("cp.async.cg.shared.global [%0], [%1], 16;" :: "r"(dst), "l"(src))
#define CP_COMMIT() asm volatile("cp.async.commit_group;" ::: "memory")
#define CP_WAIT(n)  asm volatile("cp.async.wait_group %0;" :: "n"(n) : "memory")

__device__ __forceinline__ void ldsm4(uint32_t* r, uint32_t addr) {
    asm volatile("ldmatrix.sync.aligned.m8n8.x4.shared.b16 {%0,%1,%2,%3}, [%4];"
        : "=r"(r[0]), "=r"(r[1]), "=r"(r[2]), "=r"(r[3]) : "r"(addr));
}
__device__ __forceinline__ void ldsm4t(uint32_t* r, uint32_t addr) {
    asm volatile("ldmatrix.sync.aligned.m8n8.x4.trans.shared.b16 {%0,%1,%2,%3}, [%4];"
        : "=r"(r[0]), "=r"(r[1]), "=r"(r[2]), "=r"(r[3]) : "r"(addr));
}
__device__ __forceinline__ void mma16816(float* d, const uint32_t* a,
                                         uint32_t b0, uint32_t b1) {
    asm volatile("mma.sync.aligned.m16n8k16.row.col.f32.bf16.bf16.f32 "
        "{%0,%1,%2,%3}, {%4,%5,%6,%7}, {%8,%9}, {%0,%1,%2,%3};"
        : "+f"(d[0]), "+f"(d[1]), "+f"(d[2]), "+f"(d[3])
        : "r"(a[0]), "r"(a[1]), "r"(a[2]), "r"(a[3]), "r"(b0), "r"(b1));
}
// split two floats into packed bf16x2 hi and residual lo
__device__ __forceinline__ void split2(float x, float y, uint32_t& hi, uint32_t& lo) {
    __nv_bfloat16 hx = __float2bfloat16(x), hy = __float2bfloat16(y);
    __nv_bfloat16 lx = __float2bfloat16(x - __bfloat162float(hx));
    __nv_bfloat16 ly = __float2bfloat16(y - __bfloat162float(hy));
    __nv_bfloat162 H(hx, hy), L(lx, ly);
    hi = *(uint32_t*)&H;
    lo = *(uint32_t*)&L;
}

// ---------------- convert kernels ------------------------------------------
__global__ void conv_split_kernel(const float* __restrict__ src)
{
    __nv_bfloat16* hi = &gA_hi[0][0];
    __nv_bfloat16* lo = &gA_lo[0][0];
    int i = (blockIdx.x * blockDim.x + threadIdx.x) * 4;
    float4 v = *(const float4*)(src + i);
    uint32_t h01, l01, h23, l23;
    split2(v.x, v.y, h01, l01);
    split2(v.z, v.w, h23, l23);
    *(uint32_t*)(hi + i)     = h01;
    *(uint32_t*)(hi + i + 2) = h23;
    *(uint32_t*)(lo + i)     = l01;
    *(uint32_t*)(lo + i + 2) = l23;
}

template<int MODE>   // W[K][N] -> out[N][K] hi/lo.  0: W_qkv ; 1: W_proj
__global__ void transpose_split_kernel(const float* __restrict__ W)
{
    const int N = (MODE == 0) ? 3 * DIM : DIM;
    __nv_bfloat16* hi = (MODE == 0) ? &gBq_hi[0][0] : &gBp_hi[0][0];
    __nv_bfloat16* lo = (MODE == 0) ? &gBq_lo[0][0] : &gBp_lo[0][0];
    __shared__ float t[32][33];
    const int n0 = blockIdx.x * 32, k0 = blockIdx.y * 32;
    const int tx = threadIdx.x, ty = threadIdx.y;
    #pragma unroll
    for (int i = ty; i < 32; i += 8)
        t[i][tx] = W[(size_t)(k0 + i) * N + n0 + tx];
    __syncthreads();
    #pragma unroll
    for (int i = ty; i < 32; i += 8) {
        float v = t[tx][i];
        __nv_bfloat16 h = __float2bfloat16(v);
        __nv_bfloat16 l = __float2bfloat16(v - __bfloat162float(h));
        hi[(size_t)(n0 + i) * DIM + k0 + tx] = h;
        lo[(size_t)(n0 + i) * DIM + k0 + tx] = l;
    }
}

// ---------------- warp-mma bf16 3-split GEMM -------------------------------
// CTA tile 64(m) x 128(n), 256 threads = 8 warps in 2x4 grid, warp tile 32x32.
// ~75 regs/thread -> 3 CTAs/SM (24 warps, occ 37.5%). smem 60KB/CTA, 2-stage.
// MODE 0: A=gA,B=gBq -> split bf16 scatter into gQ/gK/gV (q*0.125)
// MODE 1: A=gY,B=gBp -> fp32 C
#define KCHUNK   32
#define A_TILE_B (64 * 40 * 2)           // 5120 B
#define B_TILE_B (128 * 40 * 2)          // 10240 B
#define STAGE_B  (2 * A_TILE_B + 2 * B_TILE_B)   // 30720 B
#define GEMM_SMEM (2 * STAGE_B)          // 61440 B

template<int MODE>
__global__ __launch_bounds__(256, 3)
void mma_gemm_kernel(float* __restrict__ C, int N)
{
    extern __shared__ char smem[];
    const uint32_t sb = smem_u32(smem);
    const int tid = threadIdx.x;
    const int bm = blockIdx.y, bn = blockIdx.x;
    const int w = tid >> 5, lane = tid & 31;
    const int wm = w >> 2, wn = w & 3;            // 2 x 4 warp grid, 32x32 tiles
    const int lrow = lane & 15, lcol8 = (lane >> 4) * 8;
    const int gid = lane >> 2, tig = lane & 3;

    const __nv_bfloat16* Ahi = (MODE == 0) ? &gA_hi[0][0] : &gY_hi[0][0];
    const __nv_bfloat16* Alo = (MODE == 0) ? &gA_lo[0][0] : &gY_lo[0][0];
    const __nv_bfloat16* Bhi = (MODE == 0) ? &gBq_hi[0][0] : &gBp_hi[0][0];
    const __nv_bfloat16* Blo = (MODE == 0) ? &gBq_lo[0][0] : &gBp_lo[0][0];

    // 1536 cp slots: A(h,l) 64x4seg = 512, B(h,l) 128x4seg = 1024. 6/thread.
    auto issue_load = [&](int c) {
        const uint32_t st = sb + (uint32_t)(c & 1) * STAGE_B;
        const int k0 = c * KCHUNK;
        #pragma unroll
        for (int it = 0; it < 6; ++it) {
            const int idx = it * 256 + tid;
            const __nv_bfloat16* src;
            uint32_t dst;
            if (it < 2) {             // idx < 512 : A tiles
                const int t = idx >> 8, r = (idx & 255) >> 2, seg = idx & 3;
                src = (t == 0 ? Ahi : Alo)
                    + (size_t)(bm * 64 + r) * DIM + k0 + seg * 8;
                dst = st + t * A_TILE_B + r * 80 + seg * 16;
            } else {                  // B tiles
                const int j = idx - 512;
                const int t = j >> 9, r = (j & 511) >> 2, seg = j & 3;
                src = (t == 0 ? Bhi : Blo)
                    + (size_t)(bn * 128 + r) * DIM + k0 + seg * 8;
                dst = st + 2 * A_TILE_B + t * B_TILE_B + r * 80 + seg * 16;
            }
            CP_ASYNC16(dst, src);
        }
        CP_COMMIT();
    };

    float acc[2][4][4] = {};    // [mi 16-rows][nj 8-cols][frag]

    issue_load(0);
    const int NCHUNK = DIM / KCHUNK;
    for (int c = 0; c < NCHUNK; ++c) {
        if (c + 1 < NCHUNK) { issue_load(c + 1); CP_WAIT(1); }
        else                { CP_WAIT(0); }
        __syncthreads();

        const uint32_t st = sb + (uint32_t)(c & 1) * STAGE_B;
        const uint32_t aH = st, aL = st + A_TILE_B;
        const uint32_t bH = st + 2 * A_TILE_B, bL = bH + B_TILE_B;

        #pragma unroll
        for (int kk = 0; kk < 2; ++kk) {
            const uint32_t koff = (kk * 16 + lcol8) * 2;
            uint32_t ah[2][4], al[2][4], bh[2][4], bl[2][4];
            #pragma unroll
            for (int mi = 0; mi < 2; ++mi) {
                const uint32_t ro = (wm * 32 + mi * 16 + lrow) * 80 + koff;
                ldsm4(ah[mi], aH + ro);
                ldsm4(al[mi], aL + ro);
            }
            #pragma unroll
            for (int nq = 0; nq < 2; ++nq) {
                const uint32_t ro = (wn * 32 + nq * 16 + lrow) * 80 + koff;
                ldsm4(bh[nq], bH + ro);
                ldsm4(bl[nq], bL + ro);
            }
            // pass 1: Ah x Bh
            #pragma unroll
            for (int mi = 0; mi < 2; ++mi)
                #pragma unroll
                for (int nq = 0; nq < 2; ++nq) {
                    mma16816(acc[mi][nq * 2 + 0], ah[mi], bh[nq][0], bh[nq][2]);
                    mma16816(acc[mi][nq * 2 + 1], ah[mi], bh[nq][1], bh[nq][3]);
                }
            // pass 2: Ah x Bl
            #pragma unroll
            for (int mi = 0; mi < 2; ++mi)
                #pragma unroll
                for (int nq = 0; nq < 2; ++nq) {
                    mma16816(acc[mi][nq * 2 + 0], ah[mi], bl[nq][0], bl[nq][2]);
                    mma16816(acc[mi][nq * 2 + 1], ah[mi], bl[nq][1], bl[nq][3]);
                }
            // pass 3: Al x Bh
            #pragma unroll
            for (int mi = 0; mi < 2; ++mi)
                #pragma unroll
                for (int nq = 0; nq < 2; ++nq) {
                    mma16816(acc[mi][nq * 2 + 0], al[mi], bh[nq][0], bh[nq][2]);
                    mma16816(acc[mi][nq * 2 + 1], al[mi], bh[nq][1], bh[nq][3]);
                }
        }
        __syncthreads();
    }

    #pragma unroll
    for (int mi = 0; mi < 2; ++mi)
        #pragma unroll
        for (int nj = 0; nj < 4; ++nj) {
            const int row = bm * 64 + wm * 32 + mi * 16 + gid;
            const int n = bn * 128 + wn * 32 + nj * 8 + tig * 2;
            if (MODE == 0) {
                const int which = n >> 10;
                const int h = (n >> 6) & (NUM_H - 1);
                const int cc = n & (HD - 1);
                __nv_bfloat16* dh = (which == 0) ? &gQh[h][0][0]
                                  : (which == 1) ? &gKh[h][0][0] : &gVh[h][0][0];
                __nv_bfloat16* dl = (which == 0) ? &gQl[h][0][0]
                                  : (which == 1) ? &gKl[h][0][0] : &gVl[h][0][0];
                const float s = (which == 0) ? 0.125f : 1.0f;
                uint32_t hi, lo;
                split2(acc[mi][nj][0] * s, acc[mi][nj][1] * s, hi, lo);
                *(uint32_t*)&dh[(size_t)row * HD + cc] = hi;
                *(uint32_t*)&dl[(size_t)row * HD + cc] = lo;
                split2(acc[mi][nj][2] * s, acc[mi][nj][3] * s, hi, lo);
                *(uint32_t*)&dh[(size_t)(row + 8) * HD + cc] = hi;
                *(uint32_t*)&dl[(size_t)(row + 8) * HD + cc] = lo;
            } else {
                *(float2*)&C[(size_t)row * N + n] =
                    make_float2(acc[mi][nj][0], acc[mi][nj][1]);
                *(float2*)&C[(size_t)(row + 8) * N + n] =
                    make_float2(acc[mi][nj][2], acc[mi][nj][3]);
            }
        }
}

// ---------------- flash attention, bf16 mma 3-split (unchanged) ------------
#define BR 128
#define BC 64
#define FSTR 72                                // smem row stride in halves
#define Q_TILE_H  (BR * FSTR)                  // 9216 halves
#define KV_TILE_H (BC * FSTR)                  // 4608 halves
#define STAGE_H   (4 * KV_TILE_H)              // 18432 halves
#define FLASH_SMEM_B ((2 * Q_TILE_H + 2 * STAGE_H) * 2)   // 110592 B

__global__ __launch_bounds__(256)
void flash_mma_kernel()
{
    extern __shared__ char fsm[];
    const uint32_t sb = smem_u32(fsm);
    const int tid = threadIdx.x;
    const int qb = blockIdx.x, h = blockIdx.y;
    const int w = tid >> 5, lane = tid & 31;
    const int gid = lane >> 2, tig = lane & 3;
    const int l15 = lane & 15, l16 = lane >> 4;

    // one-time Q load (Qh | Ql), own commit group
    #pragma unroll
    for (int it = 0; it < 8; ++it) {
        int idx = it * 256 + tid;
        int tile = idx >> 10, r = (idx >> 3) & 127, ch = idx & 7;
        const __nv_bfloat16* src = tile == 0 ? &gQh[h][qb * BR + r][ch * 8]
                                             : &gQl[h][qb * BR + r][ch * 8];
        CP_ASYNC16(sb + (tile * Q_TILE_H + r * FSTR + ch * 8) * 2, src);
    }
    CP_COMMIT();

    auto load_kv = [&](int kb) {
        const uint32_t st = sb + (2 * Q_TILE_H + (uint32_t)(kb & 1) * STAGE_H) * 2;
        #pragma unroll
        for (int it = 0; it < 8; ++it) {
            int idx = it * 256 + tid;
            int tile = idx >> 9, r = (idx >> 3) & 63, ch = idx & 7;
            const int tg = kb * BC + r;
            const __nv_bfloat16* src =
                (tile == 0) ? &gKh[h][tg][ch * 8] :
                (tile == 1) ? &gKl[h][tg][ch * 8] :
                (tile == 2) ? &gVh[h][tg][ch * 8] : &gVl[h][tg][ch * 8];
            CP_ASYNC16(st + (tile * KV_TILE_H + r * FSTR + ch * 8) * 2, src);
        }
        CP_COMMIT();
    };

    float o[8][4] = {};
    float m0 = -1e30f, m1 = -1e30f, l0 = 0.f, l1 = 0.f;

    load_kv(0);
    const int NKB = SEQ_T / BC;                 // 32
    for (int kb = 0; kb < NKB; ++kb) {
        if (kb + 1 < NKB) { load_kv(kb + 1); CP_WAIT(1); }
        else              { CP_WAIT(0); }
        __syncthreads();

        const uint32_t qh_b = sb, ql_b = sb + Q_TILE_H * 2;
        const uint32_t st = sb + (2 * Q_TILE_H + (uint32_t)(kb & 1) * STAGE_H) * 2;
        const uint32_t kh_b = st;
        const uint32_t kl_b = st + KV_TILE_H * 2;
        const uint32_t vh_b = st + 2 * KV_TILE_H * 2;
        const uint32_t vl_b = st + 3 * KV_TILE_H * 2;

        // ---- S = Q K^T (3-split, pass-reordered) ----
        float s[8][4] = {};
        #pragma unroll
        for (int ks = 0; ks < 4; ++ks) {
            const uint32_t qoff = ((w * 16 + l15) * FSTR + ks * 16 + l16 * 8) * 2;
            uint32_t qh[4], ql[4];
            ldsm4(qh, qh_b + qoff);
            ldsm4(ql, ql_b + qoff);
            uint32_t kh[4][4], kl[4][4];
            #pragma unroll
            for (int kg = 0; kg < 4; ++kg) {
                const uint32_t koff = ((kg * 16 + l15) * FSTR + ks * 16 + l16 * 8) * 2;
                ldsm4(kh[kg], kh_b + koff);
                ldsm4(kl[kg], kl_b + koff);
            }
            // pass 1: Qh x Kh
            #pragma unroll
            for (int kg = 0; kg < 4; ++kg) {
                mma16816(s[2 * kg],     qh, kh[kg][0], kh[kg][2]);
                mma16816(s[2 * kg + 1], qh, kh[kg][1], kh[kg][3]);
            }
            // pass 2: Qh x Kl
            #pragma unroll
            for (int kg = 0; kg < 4; ++kg) {
                mma16816(s[2 * kg],     qh, kl[kg][0], kl[kg][2]);
                mma16816(s[2 * kg + 1], qh, kl[kg][1], kl[kg][3]);
            }
            // pass 3: Ql x Kh
            #pragma unroll
            for (int kg = 0; kg < 4; ++kg) {
                mma16816(s[2 * kg],     ql, kh[kg][0], kh[kg][2]);
                mma16816(s[2 * kg + 1], ql, kh[kg][1], kh[kg][3]);
            }
        }

        // ---- online softmax (rows gid and gid+8 of this warp) ----
        float mx0 = -1e30f, mx1 = -1e30f;
        #pragma unroll
        for (int nf = 0; nf < 8; ++nf) {
            mx0 = fmaxf(mx0, fmaxf(s[nf][0], s[nf][1]));
            mx1 = fmaxf(mx1, fmaxf(s[nf][2], s[nf][3]));
        }
        mx0 = fmaxf(mx0, __shfl_xor_sync(0xffffffffu, mx0, 1));
        mx0 = fmaxf(mx0, __shfl_xor_sync(0xffffffffu, mx0, 2));
        mx1 = fmaxf(mx1, __shfl_xor_sync(0xffffffffu, mx1, 1));
        mx1 = fmaxf(mx1, __shfl_xor_sync(0xffffffffu, mx1, 2));
        const float mn0 = fmaxf(m0, mx0), mn1 = fmaxf(m1, mx1);
        const float c0 = __expf(m0 - mn0), c1 = __expf(m1 - mn1);
        m0 = mn0; m1 = mn1;
        float sum0 = 0.f, sum1 = 0.f;
        #pragma unroll
        for (int nf = 0; nf < 8; ++nf) {
            s[nf][0] = __expf(s[nf][0] - mn0);
            s[nf][1] = __expf(s[nf][1] - mn0);
            s[nf][2] = __expf(s[nf][2] - mn1);
            s[nf][3] = __expf(s[nf][3] - mn1);
            sum0 += s[nf][0] + s[nf][1];
            sum1 += s[nf][2] + s[nf][3];
        }
        sum0 += __shfl_xor_sync(0xffffffffu, sum0, 1);
        sum0 += __shfl_xor_sync(0xffffffffu, sum0, 2);
        sum1 += __shfl_xor_sync(0xffffffffu, sum1, 1);
        sum1 += __shfl_xor_sync(0xffffffffu, sum1, 2);
        l0 = l0 * c0 + sum0;
        l1 = l1 * c1 + sum1;
        #pragma unroll
        for (int nf = 0; nf < 8; ++nf) {
            o[nf][0] *= c0; o[nf][1] *= c0;
            o[nf][2] *= c1; o[nf][3] *= c1;
        }

        // ---- O += P V (3-split, pass-reordered; V via ldmatrix.trans) ----
        #pragma unroll
        for (int ks = 0; ks < 4; ++ks) {
            uint32_t ph[4], pl[4];
            split2(s[2 * ks][0],     s[2 * ks][1],     ph[0], pl[0]);
            split2(s[2 * ks][2],     s[2 * ks][3],     ph[1], pl[1]);
            split2(s[2 * ks + 1][0], s[2 * ks + 1][1], ph[2], pl[2]);
            split2(s[2 * ks + 1][2], s[2 * ks + 1][3], ph[3], pl[3]);
            uint32_t vh[4][4], vl[4][4];
            #pragma unroll
            for (int hg = 0; hg < 4; ++hg) {
                const uint32_t voff = ((ks * 16 + l15) * FSTR + hg * 16 + l16 * 8) * 2;
                ldsm4t(vh[hg], vh_b + voff);
                ldsm4t(vl[hg], vl_b + voff);
            }
            // pass 1: Ph x Vh
            #pragma unroll
            for (int hg = 0; hg < 4; ++hg) {
                mma16816(o[2 * hg],     ph, vh[hg][0], vh[hg][1]);
                mma16816(o[2 * hg + 1], ph, vh[hg][2], vh[hg][3]);
            }
            // pass 2: Ph x Vl
            #pragma unroll
            for (int hg = 0; hg < 4; ++hg) {
                mma16816(o[2 * hg],     ph, vl[hg][0], vl[hg][1]);
                mma16816(o[2 * hg + 1], ph, vl[hg][2], vl[hg][3]);
            }
            // pass 3: Pl x Vh
            #pragma unroll
            for (int hg = 0; hg < 4; ++hg) {
                mma16816(o[2 * hg],     pl, vh[hg][0], vh[hg][1]);
                mma16816(o[2 * hg + 1], pl, vh[hg][2], vh[hg][3]);
            }
        }
        __syncthreads();
    }

    // ---- epilogue: y = O / l, split to gY hi/lo ----
    const float i0 = 1.0f / l0, i1 = 1.0f / l1;
    const int t0 = qb * BR + w * 16 + gid;
    #pragma unroll
    for (int nf = 0; nf < 8; ++nf) {
        const int col = h * 64 + nf * 8 + 2 * tig;
        uint32_t hi, lo;
        split2(o[nf][0] * i0, o[nf][1] * i0, hi, lo);
        *(uint32_t*)&gY_hi[t0][col] = hi;
        *(uint32_t*)&gY_lo[t0][col] = lo;
        split2(o[nf][2] * i1, o[nf][3] * i1, hi, lo);
        *(uint32_t*)&gY_hi[t0 + 8][col] = hi;
        *(uint32_t*)&gY_lo[t0 + 8][col] = lo;
    }
}

// ---------------- launch ---------------------------------------------------
extern "C" void kernel_launch(void* const* d_in, const int* in_sizes, int n_in,
                              void* d_out, int out_size)
{
    (void)in_sizes; (void)n_in; (void)out_size;
    const float* x     = (const float*)d_in[0];
    const float* Wqkv  = (const float*)d_in[1];
    const float* Wproj = (const float*)d_in[2];
    float* out = (float*)d_out;

    cudaFuncSetAttribute(mma_gemm_kernel<0>, cudaFuncAttributeMaxDynamicSharedMemorySize,
                         GEMM_SMEM);
    cudaFuncSetAttribute(mma_gemm_kernel<1>, cudaFuncAttributeMaxDynamicSharedMemorySize,
                         GEMM_SMEM);
    cudaFuncSetAttribute(flash_mma_kernel, cudaFuncAttributeMaxDynamicSharedMemorySize,
                         FLASH_SMEM_B);

    conv_split_kernel<<<SEQ_T * DIM / 4 / 256, 256>>>(x);
    transpose_split_kernel<0><<<dim3(3 * DIM / 32, DIM / 32), dim3(32, 8)>>>(Wqkv);
    transpose_split_kernel<1><<<dim3(DIM / 32, DIM / 32), dim3(32, 8)>>>(Wproj);

    // QKV = x @ W_qkv, split-scattered into gQ/gK/gV
    mma_gemm_kernel<0><<<dim3(3 * DIM / 128, SEQ_T / 64), 256, GEMM_SMEM>>>(
        nullptr, 3 * DIM);

    // fused attention -> gY hi/lo
    flash_mma_kernel<<<dim3(SEQ_T / BR, NUM_H), 256, FLASH_SMEM_B>>>();

    // out = y @ W_proj
    mma_gemm_kernel<1><<<dim3(DIM / 128, SEQ_T / 64), 256, GEMM_SMEM>>>(
        out, DIM);
}

// round 11
// speedup vs baseline: 2.2793x; 2.2793x over previous
#include <cuda_runtime.h>
#include <cuda_fp16.h>
#include <cstdint>

#define NUM_H 16
#define SEQ_T 2048
#define DIM   1024
#define HD    64

// ---------------- scratch (__device__ globals, all fp16) -------------------
__device__ __align__(16) __half gA[SEQ_T][DIM];
__device__ __align__(16) __half gBq[3 * DIM][DIM];   // [N][K]
__device__ __align__(16) __half gBp[DIM][DIM];
__device__ __align__(16) __half gY[SEQ_T][DIM];
__device__ __align__(16) __half gQ[NUM_H][SEQ_T][HD];   // pre-scaled by 1/8
__device__ __align__(16) __half gK[NUM_H][SEQ_T][HD];
__device__ __align__(16) __half gV[NUM_H][SEQ_T][HD];

// ---------------- PTX helpers ----------------------------------------------
__device__ __forceinline__ uint32_t smem_u32(const void* p) {
    uint32_t a;
    asm("{ .reg .u64 t; cvta.to.shared.u64 t, %1; cvt.u32.u64 %0, t; }" : "=r"(a) : "l"(p));
    return a;
}
#define CP_ASYNC16(dst, src) \
    asm volatile("cp.async.cg.shared.global [%0], [%1], 16;" :: "r"(dst), "l"(src))
#define CP_COMMIT() asm volatile("cp.async.commit_group;" ::: "memory")
#define CP_WAIT(n)  asm volatile("cp.async.wait_group %0;" :: "n"(n) : "memory")

__device__ __forceinline__ void ldsm4(uint32_t* r, uint32_t addr) {
    asm volatile("ldmatrix.sync.aligned.m8n8.x4.shared.b16 {%0,%1,%2,%3}, [%4];"
        : "=r"(r[0]), "=r"(r[1]), "=r"(r[2]), "=r"(r[3]) : "r"(addr));
}
__device__ __forceinline__ void ldsm4t(uint32_t* r, uint32_t addr) {
    asm volatile("ldmatrix.sync.aligned.m8n8.x4.trans.shared.b16 {%0,%1,%2,%3}, [%4];"
        : "=r"(r[0]), "=r"(r[1]), "=r"(r[2]), "=r"(r[3]) : "r"(addr));
}
__device__ __forceinline__ void mma16816(float* d, const uint32_t* a,
                                         uint32_t b0, uint32_t b1) {
    asm volatile("mma.sync.aligned.m16n8k16.row.col.f32.f16.f16.f32 "
        "{%0,%1,%2,%3}, {%4,%5,%6,%7}, {%8,%9}, {%0,%1,%2,%3};"
        : "+f"(d[0]), "+f"(d[1]), "+f"(d[2]), "+f"(d[3])
        : "r"(a[0]), "r"(a[1]), "r"(a[2]), "r"(a[3]), "r"(b0), "r"(b1));
}
__device__ __forceinline__ uint32_t pack2h(float x, float y) {
    __half2 t = __floats2half2_rn(x, y);
    return *(uint32_t*)&t;
}

// ---------------- convert kernels ------------------------------------------
__global__ void conv_f16_kernel(const float* __restrict__ src)
{
    __half* dst = &gA[0][0];
    int i = (blockIdx.x * blockDim.x + threadIdx.x) * 4;
    float4 v = *(const float4*)(src + i);
    *(uint32_t*)(dst + i)     = pack2h(v.x, v.y);
    *(uint32_t*)(dst + i + 2) = pack2h(v.z, v.w);
}

template<int MODE>   // W[K][N] -> out[N][K] fp16.  0: W_qkv ; 1: W_proj
__global__ void transpose_f16_kernel(const float* __restrict__ W)
{
    const int N = (MODE == 0) ? 3 * DIM : DIM;
    __half* dst = (MODE == 0) ? &gBq[0][0] : &gBp[0][0];
    __shared__ float t[32][33];
    const int n0 = blockIdx.x * 32, k0 = blockIdx.y * 32;
    const int tx = threadIdx.x, ty = threadIdx.y;
    #pragma unroll
    for (int i = ty; i < 32; i += 8)
        t[i][tx] = W[(size_t)(k0 + i) * N + n0 + tx];
    __syncthreads();
    #pragma unroll
    for (int i = ty; i < 32; i += 8)
        dst[(size_t)(n0 + i) * DIM + k0 + tx] = __float2half_rn(t[tx][i]);
}

// ---------------- warp-mma fp16 single-pass GEMM ---------------------------
// CTA 128x128, 256 threads, 4x2 warp grid, warp tile 32x64.
// MODE 0: A=gA,B=gBq -> fp16 scatter into gQ/gK/gV (q*0.125)
// MODE 1: A=gY,B=gBp -> fp32 C
#define KCHUNK   32
#define RSTRIDE  40
#define TILE_B   (128 * RSTRIDE * 2)     // 10240 B per operand tile
#define STAGE_B  (2 * TILE_B)            // A | B
#define GEMM_SMEM (2 * STAGE_B)          // 40960 B

template<int MODE>
__global__ __launch_bounds__(256)
void mma_gemm_kernel(float* __restrict__ C, int N)
{
    extern __shared__ char smem[];
    const uint32_t sb = smem_u32(smem);
    const int tid = threadIdx.x;
    const int bm = blockIdx.y, bn = blockIdx.x;
    const int w = tid >> 5, lane = tid & 31;
    const int wm = w >> 1, wn = w & 1;            // 4 x 2 warp grid
    const int lrow = lane & 15, lcol8 = (lane >> 4) * 8;
    const int gid = lane >> 2, tig = lane & 3;

    const __half* A = (MODE == 0) ? &gA[0][0] : &gY[0][0];
    const __half* B = (MODE == 0) ? &gBq[0][0] : &gBp[0][0];

    // 1024 cp slots: 2 tiles x 128 rows x 4 segs; 4 per thread
    auto issue_load = [&](int c) {
        const uint32_t st = sb + (uint32_t)(c & 1) * STAGE_B;
        const int k0 = c * KCHUNK;
        #pragma unroll
        for (int it = 0; it < 4; ++it) {
            const int idx = it * 256 + tid;
            const int t = idx >> 9;                 // 0=A, 1=B
            const int r = (idx & 511) >> 2;
            const int seg = idx & 3;
            const __half* src = (t == 0 ? A : B)
                + (size_t)(((t == 0 ? bm : bn) * 128) + r) * DIM + k0 + seg * 8;
            const uint32_t dst = st + t * TILE_B + r * (RSTRIDE * 2) + seg * 16;
            CP_ASYNC16(dst, src);
        }
        CP_COMMIT();
    };

    float acc[2][8][4] = {};

    issue_load(0);
    const int NCHUNK = DIM / KCHUNK;
    for (int c = 0; c < NCHUNK; ++c) {
        if (c + 1 < NCHUNK) { issue_load(c + 1); CP_WAIT(1); }
        else                { CP_WAIT(0); }
        __syncthreads();

        const uint32_t st = sb + (uint32_t)(c & 1) * STAGE_B;
        const uint32_t aB = st, bB = st + TILE_B;

        #pragma unroll
        for (int kk = 0; kk < 2; ++kk) {
            const uint32_t koff = (kk * 16 + lcol8) * 2;
            uint32_t af[2][4], bf[4][4];
            #pragma unroll
            for (int mi = 0; mi < 2; ++mi) {
                const uint32_t ro = (wm * 32 + mi * 16 + lrow) * (RSTRIDE * 2) + koff;
                ldsm4(af[mi], aB + ro);
            }
            #pragma unroll
            for (int nq = 0; nq < 4; ++nq) {
                const uint32_t ro = (wn * 64 + nq * 16 + lrow) * (RSTRIDE * 2) + koff;
                ldsm4(bf[nq], bB + ro);
            }
            #pragma unroll
            for (int mi = 0; mi < 2; ++mi)
                #pragma unroll
                for (int nq = 0; nq < 4; ++nq) {
                    mma16816(acc[mi][nq * 2 + 0], af[mi], bf[nq][0], bf[nq][2]);
                    mma16816(acc[mi][nq * 2 + 1], af[mi], bf[nq][1], bf[nq][3]);
                }
        }
        __syncthreads();
    }

    #pragma unroll
    for (int mi = 0; mi < 2; ++mi)
        #pragma unroll
        for (int nj = 0; nj < 8; ++nj) {
            const int row = bm * 128 + wm * 32 + mi * 16 + gid;
            const int n = bn * 128 + wn * 64 + nj * 8 + tig * 2;
            if (MODE == 0) {
                const int which = n >> 10;
                const int h = (n >> 6) & (NUM_H - 1);
                const int cc = n & (HD - 1);
                __half* dst = (which == 0) ? &gQ[h][0][0]
                            : (which == 1) ? &gK[h][0][0] : &gV[h][0][0];
                const float s = (which == 0) ? 0.125f : 1.0f;
                *(uint32_t*)&dst[(size_t)row * HD + cc] =
                    pack2h(acc[mi][nj][0] * s, acc[mi][nj][1] * s);
                *(uint32_t*)&dst[(size_t)(row + 8) * HD + cc] =
                    pack2h(acc[mi][nj][2] * s, acc[mi][nj][3] * s);
            } else {
                *(float2*)&C[(size_t)row * N + n] =
                    make_float2(acc[mi][nj][0], acc[mi][nj][1]);
                *(float2*)&C[(size_t)(row + 8) * N + n] =
                    make_float2(acc[mi][nj][2], acc[mi][nj][3]);
            }
        }
}

// ---------------- flash attention, fp16 mma single-pass --------------------
// CTA: 128 queries x 1 head. 8 warps, warp = 16 query rows.
// Bc=64 keys/iter, double-buffered K|V via cp.async.
#define BR 128
#define BC 64
#define FSTR 72                                // smem row stride in halves
#define Q_TILE_H  (BR * FSTR)                  // 9216 halves
#define KV_TILE_H (BC * FSTR)                  // 4608 halves
#define STAGE_H   (2 * KV_TILE_H)              // K | V
#define FLASH_SMEM_B ((Q_TILE_H + 2 * STAGE_H) * 2)   // 55296 B

__global__ __launch_bounds__(256)
void flash_mma_kernel()
{
    extern __shared__ char fsm[];
    const uint32_t sb = smem_u32(fsm);
    const int tid = threadIdx.x;
    const int qb = blockIdx.x, h = blockIdx.y;
    const int w = tid >> 5, lane = tid & 31;
    const int gid = lane >> 2, tig = lane & 3;
    const int l15 = lane & 15, l16 = lane >> 4;

    // one-time Q load: 1024 slots (128 rows x 8 chunks), 4 per thread
    #pragma unroll
    for (int it = 0; it < 4; ++it) {
        int idx = it * 256 + tid;
        int r = idx >> 3, ch = idx & 7;
        CP_ASYNC16(sb + (r * FSTR + ch * 8) * 2, &gQ[h][qb * BR + r][ch * 8]);
    }
    CP_COMMIT();

    auto load_kv = [&](int kb) {
        const uint32_t st = sb + (Q_TILE_H + (uint32_t)(kb & 1) * STAGE_H) * 2;
        #pragma unroll
        for (int it = 0; it < 4; ++it) {
            int idx = it * 256 + tid;
            int tile = idx >> 9, r = (idx >> 3) & 63, ch = idx & 7;
            const int tg = kb * BC + r;
            const __half* src = (tile == 0) ? &gK[h][tg][ch * 8] : &gV[h][tg][ch * 8];
            CP_ASYNC16(st + (tile * KV_TILE_H + r * FSTR + ch * 8) * 2, src);
        }
        CP_COMMIT();
    };

    float o[8][4] = {};
    float m0 = -1e30f, m1 = -1e30f, l0 = 0.f, l1 = 0.f;

    load_kv(0);
    const int NKB = SEQ_T / BC;                 // 32
    for (int kb = 0; kb < NKB; ++kb) {
        if (kb + 1 < NKB) { load_kv(kb + 1); CP_WAIT(1); }
        else              { CP_WAIT(0); }
        __syncthreads();

        const uint32_t q_b = sb;
        const uint32_t st = sb + (Q_TILE_H + (uint32_t)(kb & 1) * STAGE_H) * 2;
        const uint32_t k_b = st;
        const uint32_t v_b = st + KV_TILE_H * 2;

        // ---- S = Q K^T ----
        float s[8][4] = {};
        #pragma unroll
        for (int ks = 0; ks < 4; ++ks) {
            const uint32_t qoff = ((w * 16 + l15) * FSTR + ks * 16 + l16 * 8) * 2;
            uint32_t qf[4];
            ldsm4(qf, q_b + qoff);
            uint32_t kf[4][4];
            #pragma unroll
            for (int kg = 0; kg < 4; ++kg) {
                const uint32_t koff = ((kg * 16 + l15) * FSTR + ks * 16 + l16 * 8) * 2;
                ldsm4(kf[kg], k_b + koff);
            }
            #pragma unroll
            for (int kg = 0; kg < 4; ++kg) {
                mma16816(s[2 * kg],     qf, kf[kg][0], kf[kg][2]);
                mma16816(s[2 * kg + 1], qf, kf[kg][1], kf[kg][3]);
            }
        }

        // ---- online softmax (rows gid and gid+8 of this warp) ----
        float mx0 = -1e30f, mx1 = -1e30f;
        #pragma unroll
        for (int nf = 0; nf < 8; ++nf) {
            mx0 = fmaxf(mx0, fmaxf(s[nf][0], s[nf][1]));
            mx1 = fmaxf(mx1, fmaxf(s[nf][2], s[nf][3]));
        }
        mx0 = fmaxf(mx0, __shfl_xor_sync(0xffffffffu, mx0, 1));
        mx0 = fmaxf(mx0, __shfl_xor_sync(0xffffffffu, mx0, 2));
        mx1 = fmaxf(mx1, __shfl_xor_sync(0xffffffffu, mx1, 1));
        mx1 = fmaxf(mx1, __shfl_xor_sync(0xffffffffu, mx1, 2));
        const float mn0 = fmaxf(m0, mx0), mn1 = fmaxf(m1, mx1);
        const float c0 = __expf(m0 - mn0), c1 = __expf(m1 - mn1);
        m0 = mn0; m1 = mn1;
        float sum0 = 0.f, sum1 = 0.f;
        #pragma unroll
        for (int nf = 0; nf < 8; ++nf) {
            s[nf][0] = __expf(s[nf][0] - mn0);
            s[nf][1] = __expf(s[nf][1] - mn0);
            s[nf][2] = __expf(s[nf][2] - mn1);
            s[nf][3] = __expf(s[nf][3] - mn1);
            sum0 += s[nf][0] + s[nf][1];
            sum1 += s[nf][2] + s[nf][3];
        }
        sum0 += __shfl_xor_sync(0xffffffffu, sum0, 1);
        sum0 += __shfl_xor_sync(0xffffffffu, sum0, 2);
        sum1 += __shfl_xor_sync(0xffffffffu, sum1, 1);
        sum1 += __shfl_xor_sync(0xffffffffu, sum1, 2);
        l0 = l0 * c0 + sum0;
        l1 = l1 * c1 + sum1;
        #pragma unroll
        for (int nf = 0; nf < 8; ++nf) {
            o[nf][0] *= c0; o[nf][1] *= c0;
            o[nf][2] *= c1; o[nf][3] *= c1;
        }

        // ---- O += P V (P packed from S accumulator, V via ldmatrix.trans) --
        #pragma unroll
        for (int ks = 0; ks < 4; ++ks) {
            uint32_t pf[4];
            pf[0] = pack2h(s[2 * ks][0],     s[2 * ks][1]);
            pf[1] = pack2h(s[2 * ks][2],     s[2 * ks][3]);
            pf[2] = pack2h(s[2 * ks + 1][0], s[2 * ks + 1][1]);
            pf[3] = pack2h(s[2 * ks + 1][2], s[2 * ks + 1][3]);
            uint32_t vf[4][4];
            #pragma unroll
            for (int hg = 0; hg < 4; ++hg) {
                const uint32_t voff = ((ks * 16 + l15) * FSTR + hg * 16 + l16 * 8) * 2;
                ldsm4t(vf[hg], v_b + voff);
            }
            #pragma unroll
            for (int hg = 0; hg < 4; ++hg) {
                mma16816(o[2 * hg],     pf, vf[hg][0], vf[hg][1]);
                mma16816(o[2 * hg + 1], pf, vf[hg][2], vf[hg][3]);
            }
        }
        __syncthreads();
    }

    // ---- epilogue: y = O / l -> gY fp16 ----
    const float i0 = 1.0f / l0, i1 = 1.0f / l1;
    const int t0 = qb * BR + w * 16 + gid;
    #pragma unroll
    for (int nf = 0; nf < 8; ++nf) {
        const int col = h * 64 + nf * 8 + 2 * tig;
        *(uint32_t*)&gY[t0][col]     = pack2h(o[nf][0] * i0, o[nf][1] * i0);
        *(uint32_t*)&gY[t0 + 8][col] = pack2h(o[nf][2] * i1, o[nf][3] * i1);
    }
}

// ---------------- launch ---------------------------------------------------
extern "C" void kernel_launch(void* const* d_in, const int* in_sizes, int n_in,
                              void* d_out, int out_size)
{
    (void)in_sizes; (void)n_in; (void)out_size;
    const float* x     = (const float*)d_in[0];
    const float* Wqkv  = (const float*)d_in[1];
    const float* Wproj = (const float*)d_in[2];
    float* out = (float*)d_out;

    cudaFuncSetAttribute(flash_mma_kernel, cudaFuncAttributeMaxDynamicSharedMemorySize,
                         FLASH_SMEM_B);

    conv_f16_kernel<<<SEQ_T * DIM / 4 / 256, 256>>>(x);
    transpose_f16_kernel<0><<<dim3(3 * DIM / 32, DIM / 32), dim3(32, 8)>>>(Wqkv);
    transpose_f16_kernel<1><<<dim3(DIM / 32, DIM / 32), dim3(32, 8)>>>(Wproj);

    // QKV = x @ W_qkv -> fp16 gQ/gK/gV
    mma_gemm_kernel<0><<<dim3(3 * DIM / 128, SEQ_T / 128), 256, GEMM_SMEM>>>(
        nullptr, 3 * DIM);

    // fused attention -> gY fp16
    flash_mma_kernel<<<dim3(SEQ_T / BR, NUM_H), 256, FLASH_SMEM_B>>>();

    // out = y @ W_proj (fp32 out)
    mma_gemm_kernel<1><<<dim3(DIM / 128, SEQ_T / 128), 256, GEMM_SMEM>>>(
        out, DIM);
}

// round 13
// speedup vs baseline: 2.2809x; 1.0007x over previous
#include <cuda_runtime.h>
#include <cuda_fp16.h>
#include <cstdint>

#define NUM_H 16
#define SEQ_T 2048
#define DIM   1024
#define HD    64

// ---------------- scratch (__device__ globals, all fp16) -------------------
__device__ __align__(16) __half gA[SEQ_T][DIM];
__device__ __align__(16) __half gBq[3 * DIM][DIM];   // [N][K]
__device__ __align__(16) __half gBp[DIM][DIM];
__device__ __align__(16) __half gY[SEQ_T][DIM];
__device__ __align__(16) __half gQ[NUM_H][SEQ_T][HD];   // pre-scaled by 1/8
__device__ __align__(16) __half gK[NUM_H][SEQ_T][HD];
__device__ __align__(16) __half gV[NUM_H][SEQ_T][HD];

// ---------------- PTX helpers ----------------------------------------------
__device__ __forceinline__ uint32_t smem_u32(const void* p) {
    uint32_t a;
    asm("{ .reg .u64 t; cvta.to.shared.u64 t, %1; cvt.u32.u64 %0, t; }" : "=r"(a) : "l"(p));
    return a;
}
#define CP_ASYNC16(dst, src) \
    asm volatile("cp.async.cg.shared.global [%0], [%1], 16;" :: "r"(dst), "l"(src))
#define CP_COMMIT() asm volatile("cp.async.commit_group;" ::: "memory")
#define CP_WAIT(n)  asm volatile("cp.async.wait_group %0;" :: "n"(n) : "memory")

__device__ __forceinline__ void ldsm4(uint32_t* r, uint32_t addr) {
    asm volatile("ldmatrix.sync.aligned.m8n8.x4.shared.b16 {%0,%1,%2,%3}, [%4];"
        : "=r"(r[0]), "=r"(r[1]), "=r"(r[2]), "=r"(r[3]) : "r"(addr));
}
__device__ __forceinline__ void ldsm4t(uint32_t* r, uint32_t addr) {
    asm volatile("ldmatrix.sync.aligned.m8n8.x4.trans.shared.b16 {%0,%1,%2,%3}, [%4];"
        : "=r"(r[0]), "=r"(r[1]), "=r"(r[2]), "=r"(r[3]) : "r"(addr));
}
__device__ __forceinline__ void mma16816(float* d, const uint32_t* a,
                                         uint32_t b0, uint32_t b1) {
    asm volatile("mma.sync.aligned.m16n8k16.row.col.f32.f16.f16.f32 "
        "{%0,%1,%2,%3}, {%4,%5,%6,%7}, {%8,%9}, {%0,%1,%2,%3};"
        : "+f"(d[0]), "+f"(d[1]), "+f"(d[2]), "+f"(d[3])
        : "r"(a[0]), "r"(a[1]), "r"(a[2]), "r"(a[3]), "r"(b0), "r"(b1));
}
__device__ __forceinline__ uint32_t pack2h(float x, float y) {
    __half2 t = __floats2half2_rn(x, y);
    return *(uint32_t*)&t;
}

// ---------------- convert kernels ------------------------------------------
__global__ void conv_f16_kernel(const float* __restrict__ src)
{
    __half* dst = &gA[0][0];
    int i = (blockIdx.x * blockDim.x + threadIdx.x) * 4;
    float4 v = *(const float4*)(src + i);
    *(uint32_t*)(dst + i)     = pack2h(v.x, v.y);
    *(uint32_t*)(dst + i + 2) = pack2h(v.z, v.w);
}

template<int MODE>   // W[K][N] -> out[N][K] fp16.  0: W_qkv ; 1: W_proj
__global__ void transpose_f16_kernel(const float* __restrict__ W)
{
    const int N = (MODE == 0) ? 3 * DIM : DIM;
    __half* dst = (MODE == 0) ? &gBq[0][0] : &gBp[0][0];
    __shared__ float t[32][33];
    const int n0 = blockIdx.x * 32, k0 = blockIdx.y * 32;
    const int tx = threadIdx.x, ty = threadIdx.y;
    #pragma unroll
    for (int i = ty; i < 32; i += 8)
        t[i][tx] = W[(size_t)(k0 + i) * N + n0 + tx];
    __syncthreads();
    #pragma unroll
    for (int i = ty; i < 32; i += 8)
        dst[(size_t)(n0 + i) * DIM + k0 + tx] = __float2half_rn(t[tx][i]);
}

// ---------------- warp-mma fp16 GEMM, 3-stage cp.async pipeline ------------
// CTA 128x128, 256 threads, 4x2 warp grid, warp tile 32x64.
// MODE 0: A=gA,B=gBq -> fp16 scatter into gQ/gK/gV (q*0.125)
// MODE 1: A=gY,B=gBp -> fp32 C
#define KCHUNK   32
#define RSTRIDE  40
#define TILE_B   (128 * RSTRIDE * 2)     // 10240 B per operand tile
#define STAGE_B  (2 * TILE_B)            // A | B
#define GEMM_SMEM (3 * STAGE_B)          // 61440 B

template<int MODE>
__global__ __launch_bounds__(256)
void mma_gemm_kernel(float* __restrict__ C, int N)
{
    extern __shared__ char smem[];
    const uint32_t sb = smem_u32(smem);
    const int tid = threadIdx.x;
    const int bm = blockIdx.y, bn = blockIdx.x;
    const int w = tid >> 5, lane = tid & 31;
    const int wm = w >> 1, wn = w & 1;            // 4 x 2 warp grid
    const int lrow = lane & 15, lcol8 = (lane >> 4) * 8;
    const int gid = lane >> 2, tig = lane & 3;

    const __half* A = (MODE == 0) ? &gA[0][0] : &gY[0][0];
    const __half* B = (MODE == 0) ? &gBq[0][0] : &gBp[0][0];

    auto issue_load = [&](int c) {
        const uint32_t st = sb + (uint32_t)(c % 3) * STAGE_B;
        const int k0 = c * KCHUNK;
        #pragma unroll
        for (int it = 0; it < 4; ++it) {
            const int idx = it * 256 + tid;
            const int t = idx >> 9;                 // 0=A, 1=B
            const int r = (idx & 511) >> 2;
            const int seg = idx & 3;
            const __half* src = (t == 0 ? A : B)
                + (size_t)(((t == 0 ? bm : bn) * 128) + r) * DIM + k0 + seg * 8;
            const uint32_t dst = st + t * TILE_B + r * (RSTRIDE * 2) + seg * 16;
            CP_ASYNC16(dst, src);
        }
        CP_COMMIT();
    };

    float acc[2][8][4] = {};

    issue_load(0);
    issue_load(1);
    const int NCHUNK = DIM / KCHUNK;
    for (int c = 0; c < NCHUNK; ++c) {
        if (c + 2 < NCHUNK) { issue_load(c + 2); CP_WAIT(2); }
        else if (c + 1 < NCHUNK) { CP_WAIT(1); }
        else { CP_WAIT(0); }
        __syncthreads();

        const uint32_t st = sb + (uint32_t)(c % 3) * STAGE_B;
        const uint32_t aB = st, bB = st + TILE_B;

        #pragma unroll
        for (int kk = 0; kk < 2; ++kk) {
            const uint32_t koff = (kk * 16 + lcol8) * 2;
            uint32_t af[2][4], bf[4][4];
            #pragma unroll
            for (int mi = 0; mi < 2; ++mi) {
                const uint32_t ro = (wm * 32 + mi * 16 + lrow) * (RSTRIDE * 2) + koff;
                ldsm4(af[mi], aB + ro);
            }
            #pragma unroll
            for (int nq = 0; nq < 4; ++nq) {
                const uint32_t ro = (wn * 64 + nq * 16 + lrow) * (RSTRIDE * 2) + koff;
                ldsm4(bf[nq], bB + ro);
            }
            #pragma unroll
            for (int mi = 0; mi < 2; ++mi)
                #pragma unroll
                for (int nq = 0; nq < 4; ++nq) {
                    mma16816(acc[mi][nq * 2 + 0], af[mi], bf[nq][0], bf[nq][2]);
                    mma16816(acc[mi][nq * 2 + 1], af[mi], bf[nq][1], bf[nq][3]);
                }
        }
        __syncthreads();
    }

    #pragma unroll
    for (int mi = 0; mi < 2; ++mi)
        #pragma unroll
        for (int nj = 0; nj < 8; ++nj) {
            const int row = bm * 128 + wm * 32 + mi * 16 + gid;
            const int n = bn * 128 + wn * 64 + nj * 8 + tig * 2;
            if (MODE == 0) {
                const int which = n >> 10;
                const int h = (n >> 6) & (NUM_H - 1);
                const int cc = n & (HD - 1);
                __half* dst = (which == 0) ? &gQ[h][0][0]
                            : (which == 1) ? &gK[h][0][0] : &gV[h][0][0];
                const float s = (which == 0) ? 0.125f : 1.0f;
                *(uint32_t*)&dst[(size_t)row * HD + cc] =
                    pack2h(acc[mi][nj][0] * s, acc[mi][nj][1] * s);
                *(uint32_t*)&dst[(size_t)(row + 8) * HD + cc] =
                    pack2h(acc[mi][nj][2] * s, acc[mi][nj][3] * s);
            } else {
                *(float2*)&C[(size_t)row * N + n] =
                    make_float2(acc[mi][nj][0], acc[mi][nj][1]);
                *(float2*)&C[(size_t)(row + 8) * N + n] =
                    make_float2(acc[mi][nj][2], acc[mi][nj][3]);
            }
        }
}

// ---------------- flash attention, fp16 mma, 3-stage KV pipeline -----------
// CTA: 128 queries x 1 head. 8 warps, warp = 16 query rows.
// Bc=64 keys/iter; Q fragments hoisted into registers (loop-invariant).
#define BR 128
#define BC 64
#define FSTR 72                                // smem row stride in halves
#define Q_TILE_H  (BR * FSTR)                  // 9216 halves
#define KV_TILE_H (BC * FSTR)                  // 4608 halves
#define STAGE_H   (2 * KV_TILE_H)              // K | V
#define FLASH_SMEM_B ((Q_TILE_H + 3 * STAGE_H) * 2)   // 73728 B

__global__ __launch_bounds__(256)
void flash_mma_kernel()
{
    extern __shared__ char fsm[];
    const uint32_t sb = smem_u32(fsm);
    const int tid = threadIdx.x;
    const int qb = blockIdx.x, h = blockIdx.y;
    const int w = tid >> 5, lane = tid & 31;
    const int gid = lane >> 2, tig = lane & 3;
    const int l15 = lane & 15, l16 = lane >> 4;

    // one-time Q load: 1024 slots (128 rows x 8 chunks), 4 per thread
    #pragma unroll
    for (int it = 0; it < 4; ++it) {
        int idx = it * 256 + tid;
        int r = idx >> 3, ch = idx & 7;
        CP_ASYNC16(sb + (r * FSTR + ch * 8) * 2, &gQ[h][qb * BR + r][ch * 8]);
    }
    CP_COMMIT();

    auto load_kv = [&](int kb) {
        const uint32_t st = sb + (Q_TILE_H + (uint32_t)(kb % 3) * STAGE_H) * 2;
        #pragma unroll
        for (int it = 0; it < 4; ++it) {
            int idx = it * 256 + tid;
            int tile = idx >> 9, r = (idx >> 3) & 63, ch = idx & 7;
            const int tg = kb * BC + r;
            const __half* src = (tile == 0) ? &gK[h][tg][ch * 8] : &gV[h][tg][ch * 8];
            CP_ASYNC16(st + (tile * KV_TILE_H + r * FSTR + ch * 8) * 2, src);
        }
        CP_COMMIT();
    };

    float o[8][4] = {};
    float m0 = -1e30f, m1 = -1e30f, l0 = 0.f, l1 = 0.f;
    uint32_t qf[4][4];          // hoisted Q fragments (loop-invariant)

    load_kv(0);
    load_kv(1);
    const int NKB = SEQ_T / BC;                 // 32
    for (int kb = 0; kb < NKB; ++kb) {
        if (kb + 2 < NKB) { load_kv(kb + 2); CP_WAIT(2); }
        else if (kb + 1 < NKB) { CP_WAIT(1); }
        else { CP_WAIT(0); }
        __syncthreads();

        if (kb == 0) {          // Q arrived with the first wait; load frags once
            #pragma unroll
            for (int ks = 0; ks < 4; ++ks) {
                const uint32_t qoff = ((w * 16 + l15) * FSTR + ks * 16 + l16 * 8) * 2;
                ldsm4(qf[ks], sb + qoff);
            }
        }

        const uint32_t st = sb + (Q_TILE_H + (uint32_t)(kb % 3) * STAGE_H) * 2;
        const uint32_t k_b = st;
        const uint32_t v_b = st + KV_TILE_H * 2;

        // ---- S = Q K^T ----
        float s[8][4] = {};
        #pragma unroll
        for (int ks = 0; ks < 4; ++ks) {
            uint32_t kf[4][4];
            #pragma unroll
            for (int kg = 0; kg < 4; ++kg) {
                const uint32_t koff = ((kg * 16 + l15) * FSTR + ks * 16 + l16 * 8) * 2;
                ldsm4(kf[kg], k_b + koff);
            }
            #pragma unroll
            for (int kg = 0; kg < 4; ++kg) {
                mma16816(s[2 * kg],     qf[ks], kf[kg][0], kf[kg][2]);
                mma16816(s[2 * kg + 1], qf[ks], kf[kg][1], kf[kg][3]);
            }
        }

        // ---- online softmax (rows gid and gid+8 of this warp) ----
        float mx0 = -1e30f, mx1 = -1e30f;
        #pragma unroll
        for (int nf = 0; nf < 8; ++nf) {
            mx0 = fmaxf(mx0, fmaxf(s[nf][0], s[nf][1]));
            mx1 = fmaxf(mx1, fmaxf(s[nf][2], s[nf][3]));
        }
        mx0 = fmaxf(mx0, __shfl_xor_sync(0xffffffffu, mx0, 1));
        mx0 = fmaxf(mx0, __shfl_xor_sync(0xffffffffu, mx0, 2));
        mx1 = fmaxf(mx1, __shfl_xor_sync(0xffffffffu, mx1, 1));
        mx1 = fmaxf(mx1, __shfl_xor_sync(0xffffffffu, mx1, 2));
        const float mn0 = fmaxf(m0, mx0), mn1 = fmaxf(m1, mx1);
        const float c0 = __expf(m0 - mn0), c1 = __expf(m1 - mn1);
        m0 = mn0; m1 = mn1;
        float sum0 = 0.f, sum1 = 0.f;
        #pragma unroll
        for (int nf = 0; nf < 8; ++nf) {
            s[nf][0] = __expf(s[nf][0] - mn0);
            s[nf][1] = __expf(s[nf][1] - mn0);
            s[nf][2] = __expf(s[nf][2] - mn1);
            s[nf][3] = __expf(s[nf][3] - mn1);
            sum0 += s[nf][0] + s[nf][1];
            sum1 += s[nf][2] + s[nf][3];
        }
        sum0 += __shfl_xor_sync(0xffffffffu, sum0, 1);
        sum0 += __shfl_xor_sync(0xffffffffu, sum0, 2);
        sum1 += __shfl_xor_sync(0xffffffffu, sum1, 1);
        sum1 += __shfl_xor_sync(0xffffffffu, sum1, 2);
        l0 = l0 * c0 + sum0;
        l1 = l1 * c1 + sum1;
        #pragma unroll
        for (int nf = 0; nf < 8; ++nf) {
            o[nf][0] *= c0; o[nf][1] *= c0;
            o[nf][2] *= c1; o[nf][3] *= c1;
        }

        // ---- O += P V (P packed from S accumulator, V via ldmatrix.trans) --
        #pragma unroll
        for (int ks = 0; ks < 4; ++ks) {
            uint32_t pf[4];
            pf[0] = pack2h(s[2 * ks][0],     s[2 * ks][1]);
            pf[1] = pack2h(s[2 * ks][2],     s[2 * ks][3]);
            pf[2] = pack2h(s[2 * ks + 1][0], s[2 * ks + 1][1]);
            pf[3] = pack2h(s[2 * ks + 1][2], s[2 * ks + 1][3]);
            uint32_t vf[4][4];
            #pragma unroll
            for (int hg = 0; hg < 4; ++hg) {
                const uint32_t voff = ((ks * 16 + l15) * FSTR + hg * 16 + l16 * 8) * 2;
                ldsm4t(vf[hg], v_b + voff);
            }
            #pragma unroll
            for (int hg = 0; hg < 4; ++hg) {
                mma16816(o[2 * hg],     pf, vf[hg][0], vf[hg][1]);
                mma16816(o[2 * hg + 1], pf, vf[hg][2], vf[hg][3]);
            }
        }
        __syncthreads();
    }

    // ---- epilogue: y = O / l -> gY fp16 ----
    const float i0 = 1.0f / l0, i1 = 1.0f / l1;
    const int t0 = qb * BR + w * 16 + gid;
    #pragma unroll
    for (int nf = 0; nf < 8; ++nf) {
        const int col = h * 64 + nf * 8 + 2 * tig;
        *(uint32_t*)&gY[t0][col]     = pack2h(o[nf][0] * i0, o[nf][1] * i0);
        *(uint32_t*)&gY[t0 + 8][col] = pack2h(o[nf][2] * i1, o[nf][3] * i1);
    }
}

// ---------------- launch ---------------------------------------------------
extern "C" void kernel_launch(void* const* d_in, const int* in_sizes, int n_in,
                              void* d_out, int out_size)
{
    (void)in_sizes; (void)n_in; (void)out_size;
    const float* x     = (const float*)d_in[0];
    const float* Wqkv  = (const float*)d_in[1];
    const float* Wproj = (const float*)d_in[2];
    float* out = (float*)d_out;

    cudaFuncSetAttribute(mma_gemm_kernel<0>, cudaFuncAttributeMaxDynamicSharedMemorySize,
                         GEMM_SMEM);
    cudaFuncSetAttribute(mma_gemm_kernel<1>, cudaFuncAttributeMaxDynamicSharedMemorySize,
                         GEMM_SMEM);
    cudaFuncSetAttribute(flash_mma_kernel, cudaFuncAttributeMaxDynamicSharedMemorySize,
                         FLASH_SMEM_B);

    conv_f16_kernel<<<SEQ_T * DIM / 4 / 256, 256>>>(x);
    transpose_f16_kernel<0><<<dim3(3 * DIM / 32, DIM / 32), dim3(32, 8)>>>(Wqkv);
    transpose_f16_kernel<1><<<dim3(DIM / 32, DIM / 32), dim3(32, 8)>>>(Wproj);

    // QKV = x @ W_qkv -> fp16 gQ/gK/gV
    mma_gemm_kernel<0><<<dim3(3 * DIM / 128, SEQ_T / 128), 256, GEMM_SMEM>>>(
        nullptr, 3 * DIM);

    // fused attention -> gY fp16
    flash_mma_kernel<<<dim3(SEQ_T / BR, NUM_H), 256, FLASH_SMEM_B>>>();

    // out = y @ W_proj (fp32 out)
    mma_gemm_kernel<1><<<dim3(DIM / 128, SEQ_T / 128), 256, GEMM_SMEM>>>(
        out, DIM);
}

// round 14
// speedup vs baseline: 2.4677x; 1.0819x over previous
#include <cuda_runtime.h>
#include <cuda_fp16.h>
#include <cstdint>

#define NUM_H 16
#define SEQ_T 2048
#define DIM   1024
#define HD    64

// ---------------- scratch (__device__ globals, all fp16) -------------------
__device__ __align__(16) __half gA[SEQ_T][DIM];
__device__ __align__(16) __half gBq[3 * DIM][DIM];   // [N][K]
__device__ __align__(16) __half gBp[DIM][DIM];
__device__ __align__(16) __half gY[SEQ_T][DIM];
__device__ __align__(16) __half gQ[NUM_H][SEQ_T][HD];   // pre-scaled by 1/8
__device__ __align__(16) __half gK[NUM_H][SEQ_T][HD];
__device__ __align__(16) __half gV[NUM_H][SEQ_T][HD];

// ---------------- PTX helpers ----------------------------------------------
__device__ __forceinline__ uint32_t smem_u32(const void* p) {
    uint32_t a;
    asm("{ .reg .u64 t; cvta.to.shared.u64 t, %1; cvt.u32.u64 %0, t; }" : "=r"(a) : "l"(p));
    return a;
}
#define CP_ASYNC16(dst, src) \
    asm volatile("cp.async.cg.shared.global [%0], [%1], 16;" :: "r"(dst), "l"(src))
#define CP_COMMIT() asm volatile("cp.async.commit_group;" ::: "memory")
#define CP_WAIT(n)  asm volatile("cp.async.wait_group %0;" :: "n"(n) : "memory")

__device__ __forceinline__ void ldsm4(uint32_t* r, uint32_t addr) {
    asm volatile("ldmatrix.sync.aligned.m8n8.x4.shared.b16 {%0,%1,%2,%3}, [%4];"
        : "=r"(r[0]), "=r"(r[1]), "=r"(r[2]), "=r"(r[3]) : "r"(addr));
}
__device__ __forceinline__ void ldsm4t(uint32_t* r, uint32_t addr) {
    asm volatile("ldmatrix.sync.aligned.m8n8.x4.trans.shared.b16 {%0,%1,%2,%3}, [%4];"
        : "=r"(r[0]), "=r"(r[1]), "=r"(r[2]), "=r"(r[3]) : "r"(addr));
}
__device__ __forceinline__ void mma16816(float* d, const uint32_t* a,
                                         uint32_t b0, uint32_t b1) {
    asm volatile("mma.sync.aligned.m16n8k16.row.col.f32.f16.f16.f32 "
        "{%0,%1,%2,%3}, {%4,%5,%6,%7}, {%8,%9}, {%0,%1,%2,%3};"
        : "+f"(d[0]), "+f"(d[1]), "+f"(d[2]), "+f"(d[3])
        : "r"(a[0]), "r"(a[1]), "r"(a[2]), "r"(a[3]), "r"(b0), "r"(b1));
}
__device__ __forceinline__ uint32_t pack2h(float x, float y) {
    __half2 t = __floats2half2_rn(x, y);
    return *(uint32_t*)&t;
}

// ---------------- merged prep kernel (conv + both transposes) --------------
// blocks [0,2048): x fp32 -> gA fp16 (linear)
// blocks [2048,5120): W_qkv [K][N=3072] -> gBq [N][K] fp16 (32x32 tiles)
// blocks [5120,6144): W_proj [K][N=1024] -> gBp [N][K] fp16
#define PREP_BLOCKS (2048 + 3072 + 1024)

__global__ void prep_kernel(const float* __restrict__ x,
                            const float* __restrict__ Wqkv,
                            const float* __restrict__ Wproj)
{
    const int bid = blockIdx.x;
    const int tid = threadIdx.x;
    if (bid < 2048) {
        int i = (bid * 256 + tid) * 4;
        float4 v = *(const float4*)(x + i);
        __half* dst = &gA[0][0];
        *(uint32_t*)(dst + i)     = pack2h(v.x, v.y);
        *(uint32_t*)(dst + i + 2) = pack2h(v.z, v.w);
        return;
    }
    const float* W;
    __half* dst;
    int N, b2;
    if (bid < 5120) { W = Wqkv;  dst = &gBq[0][0]; N = 3 * DIM; b2 = bid - 2048; }
    else            { W = Wproj; dst = &gBp[0][0]; N = DIM;     b2 = bid - 5120; }
    const int nb = N / 32;
    const int n0 = (b2 % nb) * 32, k0 = (b2 / nb) * 32;
    const int tx = tid & 31, ty = tid >> 5;     // 32 x 8
    __shared__ float t[32][33];
    #pragma unroll
    for (int i = ty; i < 32; i += 8)
        t[i][tx] = W[(size_t)(k0 + i) * N + n0 + tx];
    __syncthreads();
    #pragma unroll
    for (int i = ty; i < 32; i += 8)
        dst[(size_t)(n0 + i) * DIM + k0 + tx] = __float2half_rn(t[tx][i]);
}

// ---------------- warp-mma fp16 GEMM, KCHUNK=64, 2-stage -------------------
// CTA 128x128, 256 threads, 4x2 warp grid, warp tile 32x64.
// Half the barrier/wait frequency of the KCHUNK=32 version.
// MODE 0: A=gA,B=gBq -> fp16 scatter into gQ/gK/gV (q*0.125)
// MODE 1: A=gY,B=gBp -> fp32 C
#define KCHUNK   64
#define GRSTR    72                       // halves per smem row (144 B)
#define TILE_B   (128 * GRSTR * 2)        // 18432 B per operand tile
#define STAGE_B  (2 * TILE_B)             // A | B
#define GEMM_SMEM (2 * STAGE_B)           // 73728 B

template<int MODE>
__global__ __launch_bounds__(256)
void mma_gemm_kernel(float* __restrict__ C, int N)
{
    extern __shared__ char smem[];
    const uint32_t sb = smem_u32(smem);
    const int tid = threadIdx.x;
    const int bm = blockIdx.y, bn = blockIdx.x;
    const int w = tid >> 5, lane = tid & 31;
    const int wm = w >> 1, wn = w & 1;            // 4 x 2 warp grid
    const int lrow = lane & 15, lcol8 = (lane >> 4) * 8;
    const int gid = lane >> 2, tig = lane & 3;

    const __half* A = (MODE == 0) ? &gA[0][0] : &gY[0][0];
    const __half* B = (MODE == 0) ? &gBq[0][0] : &gBp[0][0];

    // 2048 cp slots: 2 tiles x 128 rows x 8 segs; 8 per thread
    auto issue_load = [&](int c) {
        const uint32_t st = sb + (uint32_t)(c & 1) * STAGE_B;
        const int k0 = c * KCHUNK;
        #pragma unroll
        for (int it = 0; it < 8; ++it) {
            const int idx = it * 256 + tid;
            const int t = idx >> 10;                // 0=A, 1=B
            const int r = (idx >> 3) & 127;
            const int seg = idx & 7;
            const __half* src = (t == 0 ? A : B)
                + (size_t)(((t == 0 ? bm : bn) * 128) + r) * DIM + k0 + seg * 8;
            const uint32_t dst = st + t * TILE_B + r * (GRSTR * 2) + seg * 16;
            CP_ASYNC16(dst, src);
        }
        CP_COMMIT();
    };

    float acc[2][8][4] = {};

    issue_load(0);
    const int NCHUNK = DIM / KCHUNK;              // 16
    for (int c = 0; c < NCHUNK; ++c) {
        if (c + 1 < NCHUNK) { issue_load(c + 1); CP_WAIT(1); }
        else                { CP_WAIT(0); }
        __syncthreads();

        const uint32_t st = sb + (uint32_t)(c & 1) * STAGE_B;
        const uint32_t aB = st, bB = st + TILE_B;

        #pragma unroll
        for (int kk = 0; kk < 4; ++kk) {
            const uint32_t koff = (kk * 16 + lcol8) * 2;
            uint32_t af[2][4], bf[4][4];
            #pragma unroll
            for (int mi = 0; mi < 2; ++mi) {
                const uint32_t ro = (wm * 32 + mi * 16 + lrow) * (GRSTR * 2) + koff;
                ldsm4(af[mi], aB + ro);
            }
            #pragma unroll
            for (int nq = 0; nq < 4; ++nq) {
                const uint32_t ro = (wn * 64 + nq * 16 + lrow) * (GRSTR * 2) + koff;
                ldsm4(bf[nq], bB + ro);
            }
            #pragma unroll
            for (int mi = 0; mi < 2; ++mi)
                #pragma unroll
                for (int nq = 0; nq < 4; ++nq) {
                    mma16816(acc[mi][nq * 2 + 0], af[mi], bf[nq][0], bf[nq][2]);
                    mma16816(acc[mi][nq * 2 + 1], af[mi], bf[nq][1], bf[nq][3]);
                }
        }
        __syncthreads();
    }

    #pragma unroll
    for (int mi = 0; mi < 2; ++mi)
        #pragma unroll
        for (int nj = 0; nj < 8; ++nj) {
            const int row = bm * 128 + wm * 32 + mi * 16 + gid;
            const int n = bn * 128 + wn * 64 + nj * 8 + tig * 2;
            if (MODE == 0) {
                const int which = n >> 10;
                const int h = (n >> 6) & (NUM_H - 1);
                const int cc = n & (HD - 1);
                __half* dst = (which == 0) ? &gQ[h][0][0]
                            : (which == 1) ? &gK[h][0][0] : &gV[h][0][0];
                const float s = (which == 0) ? 0.125f : 1.0f;
                *(uint32_t*)&dst[(size_t)row * HD + cc] =
                    pack2h(acc[mi][nj][0] * s, acc[mi][nj][1] * s);
                *(uint32_t*)&dst[(size_t)(row + 8) * HD + cc] =
                    pack2h(acc[mi][nj][2] * s, acc[mi][nj][3] * s);
            } else {
                *(float2*)&C[(size_t)row * N + n] =
                    make_float2(acc[mi][nj][0], acc[mi][nj][1]);
                *(float2*)&C[(size_t)(row + 8) * N + n] =
                    make_float2(acc[mi][nj][2], acc[mi][nj][3]);
            }
        }
}

// ---------------- flash attention, fp16 mma, 3-stage KV pipeline -----------
// CTA: 128 queries x 1 head. 8 warps, warp = 16 query rows.
// Bc=64 keys/iter; Q fragments hoisted into registers (loop-invariant).
#define BR 128
#define BC 64
#define FSTR 72                                // smem row stride in halves
#define Q_TILE_H  (BR * FSTR)                  // 9216 halves
#define KV_TILE_H (BC * FSTR)                  // 4608 halves
#define STAGE_H   (2 * KV_TILE_H)              // K | V
#define FLASH_SMEM_B ((Q_TILE_H + 3 * STAGE_H) * 2)   // 73728 B

__global__ __launch_bounds__(256)
void flash_mma_kernel()
{
    extern __shared__ char fsm[];
    const uint32_t sb = smem_u32(fsm);
    const int tid = threadIdx.x;
    const int qb = blockIdx.x, h = blockIdx.y;
    const int w = tid >> 5, lane = tid & 31;
    const int gid = lane >> 2, tig = lane & 3;
    const int l15 = lane & 15, l16 = lane >> 4;

    // one-time Q load: 1024 slots (128 rows x 8 chunks), 4 per thread
    #pragma unroll
    for (int it = 0; it < 4; ++it) {
        int idx = it * 256 + tid;
        int r = idx >> 3, ch = idx & 7;
        CP_ASYNC16(sb + (r * FSTR + ch * 8) * 2, &gQ[h][qb * BR + r][ch * 8]);
    }
    CP_COMMIT();

    auto load_kv = [&](int kb) {
        const uint32_t st = sb + (Q_TILE_H + (uint32_t)(kb % 3) * STAGE_H) * 2;
        #pragma unroll
        for (int it = 0; it < 4; ++it) {
            int idx = it * 256 + tid;
            int tile = idx >> 9, r = (idx >> 3) & 63, ch = idx & 7;
            const int tg = kb * BC + r;
            const __half* src = (tile == 0) ? &gK[h][tg][ch * 8] : &gV[h][tg][ch * 8];
            CP_ASYNC16(st + (tile * KV_TILE_H + r * FSTR + ch * 8) * 2, src);
        }
        CP_COMMIT();
    };

    float o[8][4] = {};
    float m0 = -1e30f, m1 = -1e30f, l0 = 0.f, l1 = 0.f;
    uint32_t qf[4][4];          // hoisted Q fragments (loop-invariant)

    load_kv(0);
    load_kv(1);
    const int NKB = SEQ_T / BC;                 // 32
    for (int kb = 0; kb < NKB; ++kb) {
        if (kb + 2 < NKB) { load_kv(kb + 2); CP_WAIT(2); }
        else if (kb + 1 < NKB) { CP_WAIT(1); }
        else { CP_WAIT(0); }
        __syncthreads();

        if (kb == 0) {          // Q arrived with the first wait; load frags once
            #pragma unroll
            for (int ks = 0; ks < 4; ++ks) {
                const uint32_t qoff = ((w * 16 + l15) * FSTR + ks * 16 + l16 * 8) * 2;
                ldsm4(qf[ks], sb + qoff);
            }
        }

        const uint32_t st = sb + (Q_TILE_H + (uint32_t)(kb % 3) * STAGE_H) * 2;
        const uint32_t k_b = st;
        const uint32_t v_b = st + KV_TILE_H * 2;

        // ---- S = Q K^T ----
        float s[8][4] = {};
        #pragma unroll
        for (int ks = 0; ks < 4; ++ks) {
            uint32_t kf[4][4];
            #pragma unroll
            for (int kg = 0; kg < 4; ++kg) {
                const uint32_t koff = ((kg * 16 + l15) * FSTR + ks * 16 + l16 * 8) * 2;
                ldsm4(kf[kg], k_b + koff);
            }
            #pragma unroll
            for (int kg = 0; kg < 4; ++kg) {
                mma16816(s[2 * kg],     qf[ks], kf[kg][0], kf[kg][2]);
                mma16816(s[2 * kg + 1], qf[ks], kf[kg][1], kf[kg][3]);
            }
        }

        // ---- online softmax (rows gid and gid+8 of this warp) ----
        float mx0 = -1e30f, mx1 = -1e30f;
        #pragma unroll
        for (int nf = 0; nf < 8; ++nf) {
            mx0 = fmaxf(mx0, fmaxf(s[nf][0], s[nf][1]));
            mx1 = fmaxf(mx1, fmaxf(s[nf][2], s[nf][3]));
        }
        mx0 = fmaxf(mx0, __shfl_xor_sync(0xffffffffu, mx0, 1));
        mx0 = fmaxf(mx0, __shfl_xor_sync(0xffffffffu, mx0, 2));
        mx1 = fmaxf(mx1, __shfl_xor_sync(0xffffffffu, mx1, 1));
        mx1 = fmaxf(mx1, __shfl_xor_sync(0xffffffffu, mx1, 2));
        const float mn0 = fmaxf(m0, mx0), mn1 = fmaxf(m1, mx1);
        const float c0 = __expf(m0 - mn0), c1 = __expf(m1 - mn1);
        m0 = mn0; m1 = mn1;
        float sum0 = 0.f, sum1 = 0.f;
        #pragma unroll
        for (int nf = 0; nf < 8; ++nf) {
            s[nf][0] = __expf(s[nf][0] - mn0);
            s[nf][1] = __expf(s[nf][1] - mn0);
            s[nf][2] = __expf(s[nf][2] - mn1);
            s[nf][3] = __expf(s[nf][3] - mn1);
            sum0 += s[nf][0] + s[nf][1];
            sum1 += s[nf][2] + s[nf][3];
        }
        sum0 += __shfl_xor_sync(0xffffffffu, sum0, 1);
        sum0 += __shfl_xor_sync(0xffffffffu, sum0, 2);
        sum1 += __shfl_xor_sync(0xffffffffu, sum1, 1);
        sum1 += __shfl_xor_sync(0xffffffffu, sum1, 2);
        l0 = l0 * c0 + sum0;
        l1 = l1 * c1 + sum1;
        #pragma unroll
        for (int nf = 0; nf < 8; ++nf) {
            o[nf][0] *= c0; o[nf][1] *= c0;
            o[nf][2] *= c1; o[nf][3] *= c1;
        }

        // ---- O += P V (P packed from S accumulator, V via ldmatrix.trans) --
        #pragma unroll
        for (int ks = 0; ks < 4; ++ks) {
            uint32_t pf[4];
            pf[0] = pack2h(s[2 * ks][0],     s[2 * ks][1]);
            pf[1] = pack2h(s[2 * ks][2],     s[2 * ks][3]);
            pf[2] = pack2h(s[2 * ks + 1][0], s[2 * ks + 1][1]);
            pf[3] = pack2h(s[2 * ks + 1][2], s[2 * ks + 1][3]);
            uint32_t vf[4][4];
            #pragma unroll
            for (int hg = 0; hg < 4; ++hg) {
                const uint32_t voff = ((ks * 16 + l15) * FSTR + hg * 16 + l16 * 8) * 2;
                ldsm4t(vf[hg], v_b + voff);
            }
            #pragma unroll
            for (int hg = 0; hg < 4; ++hg) {
                mma16816(o[2 * hg],     pf, vf[hg][0], vf[hg][1]);
                mma16816(o[2 * hg + 1], pf, vf[hg][2], vf[hg][3]);
            }
        }
        __syncthreads();
    }

    // ---- epilogue: y = O / l -> gY fp16 ----
    const float i0 = 1.0f / l0, i1 = 1.0f / l1;
    const int t0 = qb * BR + w * 16 + gid;
    #pragma unroll
    for (int nf = 0; nf < 8; ++nf) {
        const int col = h * 64 + nf * 8 + 2 * tig;
        *(uint32_t*)&gY[t0][col]     = pack2h(o[nf][0] * i0, o[nf][1] * i0);
        *(uint32_t*)&gY[t0 + 8][col] = pack2h(o[nf][2] * i1, o[nf][3] * i1);
    }
}

// ---------------- launch ---------------------------------------------------
extern "C" void kernel_launch(void* const* d_in, const int* in_sizes, int n_in,
                              void* d_out, int out_size)
{
    (void)in_sizes; (void)n_in; (void)out_size;
    const float* x     = (const float*)d_in[0];
    const float* Wqkv  = (const float*)d_in[1];
    const float* Wproj = (const float*)d_in[2];
    float* out = (float*)d_out;

    cudaFuncSetAttribute(mma_gemm_kernel<0>, cudaFuncAttributeMaxDynamicSharedMemorySize,
                         GEMM_SMEM);
    cudaFuncSetAttribute(mma_gemm_kernel<1>, cudaFuncAttributeMaxDynamicSharedMemorySize,
                         GEMM_SMEM);
    cudaFuncSetAttribute(flash_mma_kernel, cudaFuncAttributeMaxDynamicSharedMemorySize,
                         FLASH_SMEM_B);

    prep_kernel<<<PREP_BLOCKS, 256>>>(x, Wqkv, Wproj);

    // QKV = x @ W_qkv -> fp16 gQ/gK/gV
    mma_gemm_kernel<0><<<dim3(3 * DIM / 128, SEQ_T / 128), 256, GEMM_SMEM>>>(
        nullptr, 3 * DIM);

    // fused attention -> gY fp16
    flash_mma_kernel<<<dim3(SEQ_T / BR, NUM_H), 256, FLASH_SMEM_B>>>();

    // out = y @ W_proj (fp32 out)
    mma_gemm_kernel<1><<<dim3(DIM / 128, SEQ_T / 128), 256, GEMM_SMEM>>>(
        out, DIM);
}